// round 16
// baseline (speedup 1.0000x reference)
#include <cuda_runtime.h>
#include <math.h>
#include <float.h>
#include <stdint.h>

// ---------------- problem constants ----------------
#define BB     4
#define CIN    256
#define HH     200
#define WW     176
#define HWTOT  (HH*WW)          // 35200
#define AA     6
#define NCLS   4
#define NREG   7
#define NCLSCH (NCLS*AA)        // 24 cls channels
#define NOUT   (NCLS*AA + NREG*AA)   // 66
#define NANCH  (AA*HWTOT)       // 211200
#define KTOP   100

// ---------------- stage-1 tiling (cls-only head) ----------------
#define TILE_HW  256
#define CK       16
#define NITER    (CIN/CK)       // 16
#define NTHREADS 256            // 8 warps
#define OT       3              // outputs per warp (8*3 = 24)
#define NPAIR    4              // hw pairs per thread
#define ESM_STRIDE 25           // epilogue row stride (24 + 1)
// smem floats: wT [0,6144) | xs0 | xs1 | xs2 (3-stage ring)
#define SM_WT    0
#define SM_XS0   6144
#define SM_XS1   10240
#define SM_XS2   14336
#define SM_ESM   6144            // esm overlays ring (6400 <= 12288)
#define SMEM_FLOATS 18432
#define SMEM_BYTES  (SMEM_FLOATS*4)   // 73728
#define CHUNK_FLOATS (CK*TILE_HW)     // 4096
#define CHUNK_F4 (CHUNK_FLOATS/4)     // 1024

// ---------------- top-k constants ----------------
#define NBINS   65536
#define CANDMAX 4096
#define CBLK    32
#define CSLICE  (NANCH/CBLK)    // 6600

// ---------------- gather smem (floats) ----------------
#define G_WT    0                 // [256][68]
#define G_BIAS  (256*68)
#define G_XCOL  (G_BIAS + 68)     // [8][256]
#define G_CHAN  (G_XCOL + 8*256)  // [8][68]
#define G_FLOATS (G_CHAN + 8*68)
#define G_BYTES  (G_FLOATS*4)

// ---------------- device scratch (zero-initialized at module load) ----------------
__device__ float    g_maxs  [(size_t)BB*NANCH];
__device__ unsigned g_hist  [BB*NBINS];   // re-zeroed by compact_kernel each run
__device__ int      g_thr   [BB];
__device__ int      g_candCnt[BB];
__device__ float    g_candV [BB*CANDMAX];
__device__ int      g_candI [BB*CANDMAX];
__device__ int      g_topI  [BB*KTOP];

// ---------------- cp.async helpers ----------------
__device__ __forceinline__ void cp16(uint32_t smem_addr, const void* gptr) {
    asm volatile("cp.async.ca.shared.global [%0], [%1], 16;"
                 :: "r"(smem_addr), "l"(gptr));
}
__device__ __forceinline__ void cp_commit() {
    asm volatile("cp.async.commit_group;");
}
template<int N> __device__ __forceinline__ void cp_wait() {
    asm volatile("cp.async.wait_group %0;" :: "n"(N));
}

// ---------------- packed f32x2 helpers ----------------
__device__ __forceinline__ void ffma2(unsigned long long& d,
                                      unsigned long long a,
                                      unsigned long long b) {
    asm("fma.rn.f32x2 %0, %1, %2, %0;" : "+l"(d) : "l"(a), "l"(b));
}
__device__ __forceinline__ unsigned long long pack_dup(float w) {
    unsigned long long r;
    asm("mov.b64 %0, {%1, %1};" : "=l"(r) : "f"(w));
    return r;
}
__device__ __forceinline__ float2 unpack2(unsigned long long v) {
    float2 f;
    asm("mov.b64 {%0, %1}, %2;" : "=f"(f.x), "=f"(f.y) : "l"(v));
    return f;
}

// ============================================================================
// Stage 1: cls-only head (GEMM 24ch via FFMA2) + slim softmax-max + histogram
// ============================================================================
__global__ __launch_bounds__(NTHREADS, 3)
void head_kernel(const float* __restrict__ x,
                 const float* __restrict__ cls_w, const float* __restrict__ cls_b)
{
    extern __shared__ float sm[];
    float* wT  = sm + SM_WT;      // [256][24]
    float* esm = sm + SM_ESM;     // [256][25], overlays ring after GEMM

    const int b    = blockIdx.y;
    const int hw0  = blockIdx.x * TILE_HW;
    const int tid  = threadIdx.x;
    const int lane = tid & 31;
    const int wrp  = tid >> 5;       // 0..7
    const int obase = wrp * OT;      // 0..21

    const float* xb = x + (size_t)b * CIN * HWTOT;
    float*   bufp[3] = { sm + SM_XS0, sm + SM_XS1, sm + SM_XS2 };
    uint32_t bufs[3];
    #pragma unroll
    for (int i = 0; i < 3; i++)
        bufs[i] = (uint32_t)__cvta_generic_to_shared(bufp[i]);

    auto issue_chunk = [&](int cc, int bi) {
        float*   dst   = bufp[bi];
        uint32_t dst_s = bufs[bi];
        for (int idx = tid; idx < CHUNK_F4; idx += NTHREADS) {
            int c   = idx >> 6;
            int col = (idx & 63) * 4;
            if (hw0 + col < HWTOT) {
                cp16(dst_s + (uint32_t)(c*TILE_HW + col)*4,
                     xb + (size_t)(cc + c)*HWTOT + hw0 + col);
            } else {
                *(float4*)(dst + c*TILE_HW + col) = make_float4(0.f,0.f,0.f,0.f);
            }
        }
        cp_commit();
    };

    // prefetch chunks 0 and 1
    issue_chunk(0, 0);
    issue_chunk(CK, 1);

    // cls weights transposed: wT[c*24 + o]
    for (int idx = tid; idx < NCLSCH*CIN; idx += NTHREADS) {
        int o = idx >> 8;
        int c = idx & 255;
        wT[c*NCLSCH + o] = cls_w[o*CIN + c];
    }

    unsigned long long acc[OT][NPAIR];
    #pragma unroll
    for (int j = 0; j < OT; j++)
        #pragma unroll
        for (int p = 0; p < NPAIR; p++) acc[j][p] = 0ull;

    #pragma unroll 1
    for (int it = 0; it < NITER; it++) {
        if (it > 0) __syncthreads();            // all warps done with iter it-1 reads
        if (it + 2 < NITER) issue_chunk((it+2)*CK, (it+2)%3);
        if (it + 2 < NITER)      cp_wait<2>();  // chunk it complete (2 in flight)
        else if (it + 1 < NITER) cp_wait<1>();
        else                     cp_wait<0>();
        __syncthreads();                        // completed data visible (+ wT 1st iter)

        const float* cur = bufp[it % 3];
        const int cc = it * CK;
        #pragma unroll
        for (int c = 0; c < CK; c++) {
            unsigned long long xp0 = *(const unsigned long long*)(cur + c*TILE_HW + 2*lane);
            unsigned long long xp1 = *(const unsigned long long*)(cur + c*TILE_HW + 2*lane + 64);
            unsigned long long xp2 = *(const unsigned long long*)(cur + c*TILE_HW + 2*lane + 128);
            unsigned long long xp3 = *(const unsigned long long*)(cur + c*TILE_HW + 2*lane + 192);
            const float* wrow = &wT[(cc + c)*NCLSCH + obase];
            #pragma unroll
            for (int j = 0; j < OT; j++) {
                unsigned long long wj = pack_dup(wrow[j]);
                ffma2(acc[j][0], wj, xp0);
                ffma2(acc[j][1], wj, xp1);
                ffma2(acc[j][2], wj, xp2);
                ffma2(acc[j][3], wj, xp3);
            }
        }
    }

    __syncthreads();   // GEMM reads done; reuse ring region as esm

    float bias[OT];
    #pragma unroll
    for (int j = 0; j < OT; j++) bias[j] = cls_b[obase + j];
    #pragma unroll
    for (int j = 0; j < OT; j++)
        #pragma unroll
        for (int p = 0; p < NPAIR; p++) {
            float2 v = unpack2(acc[j][p]);
            int m0 = 2*lane + 64*p;
            esm[(m0    )*ESM_STRIDE + obase + j] = v.x + bias[j];
            esm[(m0 + 1)*ESM_STRIDE + obase + j] = v.y + bias[j];
        }
    __syncthreads();

    // slim epilogue: one thread per hw row, 6 anchors each, no divisions
    const int hw = hw0 + tid;
    if (hw < HWTOT) {
        const float* e = esm + tid*ESM_STRIDE;   // stride 25: conflict-free
        float* mvout = g_maxs + (size_t)b*NANCH + (size_t)hw*AA;
        unsigned* hb = g_hist + b*NBINS;
        #pragma unroll
        for (int a = 0; a < AA; a++) {
            float l0 = e[a*4+0], l1 = e[a*4+1], l2 = e[a*4+2], l3 = e[a*4+3];
            float lm = fmaxf(fmaxf(l1, l2), l3);     // max FOREGROUND logit
            // p_maxfg = 1 / sum_j exp(l_j - lm); max fg term = exp(0) = 1
            float s  = __expf(l0 - lm) + __expf(l1 - lm)
                     + __expf(l2 - lm) + __expf(l3 - lm);
            float mx = __fdividef(1.f, s);
            mvout[a] = mx;

            unsigned bin   = __float_as_uint(mx) >> 16;
            unsigned amask = __activemask();
            unsigned peers = __match_any_sync(amask, bin);
            int leader = __ffs(peers) - 1;
            if (lane == leader)
                atomicAdd(&hb[bin], (unsigned)__popc(peers));
        }
    }
}

// ============================================================================
// Stage 2a: per-batch threshold find
// ============================================================================
__global__ __launch_bounds__(1024)
void threshold_kernel()
{
    const int b    = blockIdx.x;
    const int tid  = threadIdx.x;
    const int lane = tid & 31;
    const int wrp  = tid >> 5;

    __shared__ unsigned csum[1024];
    __shared__ unsigned wsum[32];

    const unsigned* h = g_hist + b*NBINS;
    {
        const uint4* h4 = (const uint4*)(h + tid*64);
        unsigned s = 0;
        #pragma unroll
        for (int k = 0; k < 16; k++) { uint4 v = h4[k]; s += v.x + v.y + v.z + v.w; }
        csum[tid] = s;
        unsigned ws = s;
        #pragma unroll
        for (int o = 16; o > 0; o >>= 1) ws += __shfl_down_sync(0xFFFFFFFFu, ws, o);
        if (lane == 0) wsum[wrp] = ws;
    }
    __syncthreads();

    if (tid == 0) {
        unsigned cum = 0;
        int w = 31;
        for (; w > 0; w--) { if (cum + wsum[w] >= (unsigned)KTOP) break; cum += wsum[w]; }
        int t = w*32 + 31;
        for (; t > w*32; t--) { if (cum + csum[t] >= (unsigned)KTOP) break; cum += csum[t]; }
        int thr = t*64;
        for (int k = 63; k >= 0; k--) {
            unsigned c = h[t*64 + k];
            if (cum + c >= (unsigned)KTOP) { thr = t*64 + k; break; }
            cum += c;
        }
        g_thr[b] = thr;
        g_candCnt[b] = 0;
    }
}

// ============================================================================
// Stage 2b: chip-wide compaction + hist re-zero
// ============================================================================
__global__ __launch_bounds__(512)
void compact_kernel()
{
    const int b   = blockIdx.y;
    const int blk = blockIdx.x;
    const int tid = threadIdx.x;

    {
        uint4* h4 = (uint4*)(g_hist + b*NBINS + blk*(NBINS/CBLK));
        if (tid < (NBINS/CBLK)/4) h4[tid] = make_uint4(0u,0u,0u,0u);
    }

    const int thr = g_thr[b];
    const float* mv = g_maxs + (size_t)b*NANCH;
    const int i0 = blk * CSLICE;
    for (int i = i0 + tid; i < i0 + CSLICE; i += 512) {
        float v = mv[i];
        if ((int)(__float_as_uint(v) >> 16) >= thr) {
            int p = atomicAdd(&g_candCnt[b], 1);
            if (p < CANDMAX) { g_candV[b*CANDMAX + p] = v; g_candI[b*CANDMAX + p] = i; }
        }
    }
}

// ============================================================================
// Stage 2c: per-batch sort -> sorted top-K indices
// ============================================================================
__global__ __launch_bounds__(1024)
void sort_kernel()
{
    const int b   = blockIdx.x;
    const int tid = threadIdx.x;

    __shared__ float sv[CANDMAX];
    __shared__ int   si[CANDMAX];

    int cnt = g_candCnt[b];
    if (cnt > CANDMAX) cnt = CANDMAX;
    int p2 = 128;
    while (p2 < cnt) p2 <<= 1;

    for (int k = tid; k < p2; k += 1024) {
        if (k < cnt) { sv[k] = g_candV[b*CANDMAX + k]; si[k] = g_candI[b*CANDMAX + k]; }
        else         { sv[k] = -FLT_MAX;               si[k] = 0x7FFFFFFF; }
    }
    __syncthreads();

    for (int k2 = 2; k2 <= p2; k2 <<= 1) {
        for (int j = k2 >> 1; j > 0; j >>= 1) {
            for (int i = tid; i < p2; i += 1024) {
                int ixj = i ^ j;
                if (ixj > i) {
                    float va = sv[i], vb = sv[ixj];
                    int   ia = si[i], ib = si[ixj];
                    bool a_below_b = (va < vb) || (va == vb && ia > ib);
                    bool up = ((i & k2) == 0);
                    if (up ? a_below_b : !a_below_b) {
                        sv[i] = vb; sv[ixj] = va; si[i] = ib; si[ixj] = ia;
                    }
                }
            }
            __syncthreads();
        }
    }

    if (tid < KTOP) g_topI[b*KTOP + tid] = si[tid];
}

// ============================================================================
// Stage 3: gather — recompute all 66 channels (exact fp32 + libm expf)
// for top-K anchors only; softmax + decode + write outputs.
// ============================================================================
__global__ __launch_bounds__(256)
void gather_kernel(float* __restrict__ outS, float* __restrict__ outB,
                   const float* __restrict__ x,
                   const float* __restrict__ cls_w, const float* __restrict__ cls_b,
                   const float* __restrict__ reg_w, const float* __restrict__ reg_b,
                   const float* __restrict__ anchors)
{
    extern __shared__ float gs[];
    float* wt   = gs + G_WT;     // [k][68]
    float* sb   = gs + G_BIAS;
    float* xcol = gs + G_XCOL;   // [8][256]
    float* chan = gs + G_CHAN;   // [8][68]

    const int b    = blockIdx.y;
    const int part = blockIdx.x;    // 0..3, 25 anchors each
    const int tid  = threadIdx.x;
    const int lane = tid & 31;
    const int wrp  = tid >> 5;      // 0..7

    for (int idx = tid; idx < NOUT*CIN; idx += 256) {
        int o = idx >> 8;
        int k = idx & 255;
        float v = (o < NCLSCH) ? cls_w[o*CIN + k] : reg_w[(o - NCLSCH)*CIN + k];
        wt[k*68 + o] = v;
    }
    if (tid < NOUT)
        sb[tid] = (tid < NCLSCH) ? cls_b[tid] : reg_b[tid - NCLSCH];
    __syncthreads();

    const float* xb = x + (size_t)b * CIN * HWTOT;

    #pragma unroll 1
    for (int it = 0; it < 4; it++) {
        int kloc = it*8 + wrp;
        int kk   = part*25 + kloc;
        bool valid = (kloc < 25) && (kk < KTOP);
        int n = 0, hw = 0, a = 0;
        if (valid) {
            n  = g_topI[b*KTOP + kk];
            hw = n / AA;
            a  = n - hw*AA;
        }
        if (valid) {
            for (int c = lane; c < CIN; c += 32)
                xcol[wrp*256 + c] = xb[(size_t)c*HWTOT + hw];
        }
        __syncwarp();
        if (valid) {
            for (int o = lane; o < NOUT; o += 32) {
                float s = sb[o];
                const float* wp = wt + o;
                const float* xc = xcol + wrp*256;
                #pragma unroll 8
                for (int k = 0; k < CIN; k++) s = fmaf(wp[k*68], xc[k], s);
                chan[wrp*68 + o] = s;
            }
        }
        __syncwarp();
        if (valid && lane == 0) {
            const float* ch = chan + wrp*68;
            float l0 = ch[a*4+0], l1 = ch[a*4+1], l2 = ch[a*4+2], l3 = ch[a*4+3];
            float m  = fmaxf(fmaxf(l0, l1), fmaxf(l2, l3));
            float e0 = expf(l0-m), e1 = expf(l1-m), e2 = expf(l2-m), e3 = expf(l3-m);
            float inv = 1.f / (e0 + e1 + e2 + e3);
            float* os = outS + ((size_t)b*KTOP + kk)*NCLS;
            os[0] = e0*inv; os[1] = e1*inv; os[2] = e2*inv; os[3] = e3*inv;

            const float* d  = ch + NCLSCH + a*NREG;
            const float* an = anchors + (size_t)n*NREG;
            float xa = an[0], ya = an[1], za = an[2];
            float dxa = an[3], dya = an[4], dza = an[5], ra = an[6];
            float diag = sqrtf(dxa*dxa + dya*dya);
            float* ob = outB + ((size_t)b*KTOP + kk)*NREG;
            ob[0] = fmaf(d[0], diag, xa);
            ob[1] = fmaf(d[1], diag, ya);
            ob[2] = fmaf(d[2], dza,  za);
            ob[3] = expf(d[3]) * dxa;
            ob[4] = expf(d[4]) * dya;
            ob[5] = expf(d[5]) * dza;
            ob[6] = d[6] + ra;
        }
        __syncwarp();
    }
}

// ============================================================================
extern "C" void kernel_launch(void* const* d_in, const int* in_sizes, int n_in,
                              void* d_out, int out_size)
{
    const float* x       = (const float*)d_in[0];
    const float* cls_w   = (const float*)d_in[1];
    const float* cls_b   = (const float*)d_in[2];
    const float* reg_w   = (const float*)d_in[3];
    const float* reg_b   = (const float*)d_in[4];
    const float* anchors = (const float*)d_in[5];

    float* outS = (float*)d_out;                 // [B, K, 4]
    float* outB = outS + (size_t)BB*KTOP*NCLS;   // [B, K, 7]

    cudaFuncSetAttribute(head_kernel, cudaFuncAttributeMaxDynamicSharedMemorySize, SMEM_BYTES);
    cudaFuncSetAttribute(gather_kernel, cudaFuncAttributeMaxDynamicSharedMemorySize, G_BYTES);

    head_kernel<<<dim3((HWTOT + TILE_HW - 1)/TILE_HW, BB), NTHREADS, SMEM_BYTES>>>(
        x, cls_w, cls_b);
    threshold_kernel<<<BB, 1024>>>();
    compact_kernel<<<dim3(CBLK, BB), 512>>>();
    sort_kernel<<<BB, 1024>>>();
    gather_kernel<<<dim3(4, BB), 256, G_BYTES>>>(outS, outB, x, cls_w, cls_b,
                                                 reg_w, reg_b, anchors);
}